// round 2
// baseline (speedup 1.0000x reference)
#include <cuda_runtime.h>

// Problem constants (fixed for this dataset)
#define FX 128   // node feature dim
#define FE 32    // edge feature dim
#define OW 256   // output row width (128 + 128)
#define MAXN 100000

// Scratch for segment-sum result [N, FE]. Static device global (no allocation).
__device__ __align__(16) float g_agg[MAXN * FE];
// Index dtype flag: 1 = int64, 0 = int32. Set by detect_kernel each launch.
__device__ int g_idx_is64;

// ---------------------------------------------------------------------------
// Detect whether edge_index is int64 or int32 by range-checking a sample
// interpreted as int64. int32 data reinterpreted as int64 produces values
// >= 2^32 (out of [0,N)) with overwhelming probability over 4096 samples.
// ---------------------------------------------------------------------------
__global__ void detect_kernel(const long long* __restrict__ idx64, int E, int N) {
    __shared__ int bad;
    if (threadIdx.x == 0) bad = 0;
    __syncthreads();
    int n = E < 4096 ? E : 4096;
    for (int i = threadIdx.x; i < n; i += blockDim.x) {
        long long v = idx64[i];
        if (v < 0 || v >= (long long)N) bad = 1;
    }
    __syncthreads();
    if (threadIdx.x == 0) g_idx_is64 = bad ? 0 : 1;
}

// ---------------------------------------------------------------------------
// Zero the agg scratch (float4 stores)
// ---------------------------------------------------------------------------
__global__ void zero_agg_kernel(int n4) {
    int i = blockIdx.x * blockDim.x + threadIdx.x;
    if (i < n4) {
        reinterpret_cast<float4*>(g_agg)[i] = make_float4(0.f, 0.f, 0.f, 0.f);
    }
}

// ---------------------------------------------------------------------------
// Scatter-add: agg[row[e], :] += edge_attr[e, :]
// One thread per (edge, 4-feature chunk): tid = e*8 + q, float4 load is
// perfectly coalesced (edge_attr row = 32 floats = 8 float4).
// ---------------------------------------------------------------------------
__global__ void scatter_kernel(const float4* __restrict__ ea,
                               const void* __restrict__ row_idx,
                               int E8, int N) {
    int tid = blockIdx.x * blockDim.x + threadIdx.x;
    if (tid >= E8) return;
    float4 v = ea[tid];
    int e = tid >> 3;
    int q = tid & 7;
    long long r;
    if (g_idx_is64)
        r = ((const long long*)row_idx)[e];
    else
        r = (long long)((const int*)row_idx)[e];
    if (r < 0 || r >= (long long)N) return;   // safety: never fault
    float* dst = g_agg + r * FE + q * 4;
    atomicAdd(dst + 0, v.x);
    atomicAdd(dst + 1, v.y);
    atomicAdd(dst + 2, v.z);
    atomicAdd(dst + 3, v.w);
}

// ---------------------------------------------------------------------------
// C[m, col0 + j] = relu( sum_k A[m,k] * B[k,j] + bias[j] ),  j in [0,128)
// Tiled SGEMM: BM=128, BN=128 (full output width), BK=16, 256 threads,
// 8x8 micro-tile per thread. A is M x K row-major, B is K x 128 row-major.
// C has row stride OW=256 (writes one half of the concatenated output).
// ---------------------------------------------------------------------------
template<int K>
__global__ __launch_bounds__(256) void gemm_bias_relu(
    const float* __restrict__ A, const float* __restrict__ B,
    const float* __restrict__ bias, float* __restrict__ C,
    int M, int col0)
{
    constexpr int BM = 128, BN = 128, BK = 16;
    __shared__ __align__(16) float As[BK][BM];   // transposed A tile
    __shared__ __align__(16) float Bs[BK][BN];

    const int tid = threadIdx.x;
    const int tx = tid & 15;        // output column group
    const int ty = tid >> 4;        // output row group
    const int m0 = blockIdx.x * BM;

    float acc[8][8];
    #pragma unroll
    for (int i = 0; i < 8; i++)
        #pragma unroll
        for (int j = 0; j < 8; j++)
            acc[i][j] = 0.f;

    for (int k0 = 0; k0 < K; k0 += BK) {
        // Load A tile (128 x 16) -> As transposed. 512 float4 slots / 256 thr.
        #pragma unroll
        for (int it = 0; it < 2; it++) {
            int idx = tid + it * 256;
            int row = idx >> 2;            // 0..127
            int c4  = (idx & 3) * 4;       // 0,4,8,12
            int m = m0 + row;
            float4 v = make_float4(0.f, 0.f, 0.f, 0.f);
            if (m < M)
                v = *reinterpret_cast<const float4*>(A + (long long)m * K + k0 + c4);
            As[c4 + 0][row] = v.x;
            As[c4 + 1][row] = v.y;
            As[c4 + 2][row] = v.z;
            As[c4 + 3][row] = v.w;
        }
        // Load B tile (16 x 128). 512 float4 slots / 256 thr.
        #pragma unroll
        for (int it = 0; it < 2; it++) {
            int idx = tid + it * 256;
            int row = idx >> 5;            // 0..15
            int c4  = (idx & 31) * 4;      // 0..124
            *reinterpret_cast<float4*>(&Bs[row][c4]) =
                *reinterpret_cast<const float4*>(B + (long long)(k0 + row) * BN + c4);
        }
        __syncthreads();

        #pragma unroll
        for (int k = 0; k < BK; k++) {
            float ra[8], rb[8];
            #pragma unroll
            for (int i = 0; i < 8; i += 4)
                *reinterpret_cast<float4*>(&ra[i]) =
                    *reinterpret_cast<const float4*>(&As[k][ty * 8 + i]);
            #pragma unroll
            for (int j = 0; j < 8; j += 4)
                *reinterpret_cast<float4*>(&rb[j]) =
                    *reinterpret_cast<const float4*>(&Bs[k][tx * 8 + j]);
            #pragma unroll
            for (int i = 0; i < 8; i++)
                #pragma unroll
                for (int j = 0; j < 8; j++)
                    acc[i][j] = fmaf(ra[i], rb[j], acc[i][j]);
        }
        __syncthreads();
    }

    // Epilogue: bias + relu, float4 stores into the proper half of out.
    #pragma unroll
    for (int i = 0; i < 8; i++) {
        int m = m0 + ty * 8 + i;
        if (m >= M) continue;
        #pragma unroll
        for (int j = 0; j < 8; j += 4) {
            int c = tx * 8 + j;
            float4 o;
            o.x = fmaxf(acc[i][j + 0] + bias[c + 0], 0.f);
            o.y = fmaxf(acc[i][j + 1] + bias[c + 1], 0.f);
            o.z = fmaxf(acc[i][j + 2] + bias[c + 2], 0.f);
            o.w = fmaxf(acc[i][j + 3] + bias[c + 3], 0.f);
            *reinterpret_cast<float4*>(C + (long long)m * OW + col0 + c) = o;
        }
    }
}

extern "C" void kernel_launch(void* const* d_in, const int* in_sizes, int n_in,
                              void* d_out, int out_size) {
    const float* x    = (const float*)d_in[0];
    const void*  eidx = d_in[1];                 // [2, E]; dtype detected on device
    const float* ea   = (const float*)d_in[2];
    const float* Wx   = (const float*)d_in[3];
    const float* bx   = (const float*)d_in[4];
    const float* We   = (const float*)d_in[5];
    const float* be   = (const float*)d_in[6];
    float*       out  = (float*)d_out;

    const int N = in_sizes[0] / FX;
    const int E = in_sizes[2] / FE;

    float* agg_ptr = nullptr;
    cudaGetSymbolAddress((void**)&agg_ptr, g_agg);

    // 0) detect index dtype (int32 vs int64)
    detect_kernel<<<1, 256>>>((const long long*)eidx, E, N);

    // 1) zero agg scratch
    int n4 = N * FE / 4;
    zero_agg_kernel<<<(n4 + 255) / 256, 256>>>(n4);

    // 2) scatter-add edge features
    int E8 = E * 8;
    scatter_kernel<<<(E8 + 255) / 256, 256>>>(
        reinterpret_cast<const float4*>(ea), eidx, E8, N);

    // 3) hx = relu(x @ Wx + bx) -> out[:, 0:128]
    int gb = (N + 127) / 128;
    gemm_bias_relu<FX><<<gb, 256>>>(x, Wx, bx, out, N, 0);

    // 4) he = relu(agg @ We + be) -> out[:, 128:256]
    gemm_bias_relu<FE><<<gb, 256>>>(agg_ptr, We, be, out, N, 128);
}

// round 3
// speedup vs baseline: 1.2749x; 1.2749x over previous
#include <cuda_runtime.h>

// Problem constants (fixed for this dataset)
#define FX 128   // node feature dim
#define FE 32    // edge feature dim
#define OW 256   // output row width (128 + 128)
#define MAXN 100000

// Scratch for segment-sum result [N, FE]. Static device global (no allocation).
__device__ __align__(16) float g_agg[MAXN * FE];
// Index dtype flag: 1 = int64, 0 = int32. Set by detect_kernel each launch.
__device__ int g_idx_is64;

// ---------------------------------------------------------------------------
// Detect whether edge_index is int64 or int32 by range-checking a sample
// interpreted as int64.
// ---------------------------------------------------------------------------
__global__ void detect_kernel(const long long* __restrict__ idx64, int E, int N) {
    __shared__ int bad;
    if (threadIdx.x == 0) bad = 0;
    __syncthreads();
    int n = E < 4096 ? E : 4096;
    for (int i = threadIdx.x; i < n; i += blockDim.x) {
        long long v = idx64[i];
        if (v < 0 || v >= (long long)N) bad = 1;
    }
    __syncthreads();
    if (threadIdx.x == 0) g_idx_is64 = bad ? 0 : 1;
}

// ---------------------------------------------------------------------------
// Zero the agg scratch (float4 stores)
// ---------------------------------------------------------------------------
__global__ void zero_agg_kernel(int n4) {
    int i = blockIdx.x * blockDim.x + threadIdx.x;
    if (i < n4) {
        reinterpret_cast<float4*>(g_agg)[i] = make_float4(0.f, 0.f, 0.f, 0.f);
    }
}

// ---------------------------------------------------------------------------
// Scatter-add: agg[row[e], :] += edge_attr[e, :]
// One thread per (edge, 4-feature chunk). Single vector RED per thread:
// red.global.add.v4.f32 (sm_90+) — 1 instruction per 16B instead of 4.
// ---------------------------------------------------------------------------
__global__ void scatter_kernel(const float4* __restrict__ ea,
                               const void* __restrict__ row_idx,
                               int E8, int N) {
    int tid = blockIdx.x * blockDim.x + threadIdx.x;
    if (tid >= E8) return;
    float4 v = ea[tid];
    int e = tid >> 3;
    int q = tid & 7;
    long long r;
    if (g_idx_is64)
        r = ((const long long*)row_idx)[e];
    else
        r = (long long)((const int*)row_idx)[e];
    if (r < 0 || r >= (long long)N) return;   // safety: never fault
    float* dst = g_agg + r * FE + q * 4;      // 16B aligned
    asm volatile("red.global.add.v4.f32 [%0], {%1, %2, %3, %4};"
                 :: "l"(dst), "f"(v.x), "f"(v.y), "f"(v.z), "f"(v.w)
                 : "memory");
}

// ---------------------------------------------------------------------------
// C[m, col0 + j] = relu( sum_k A[m,k] * B[k,j] + bias[j] ),  j in [0,128)
// Tiled SGEMM: BM=128, BN=128, BK=16, 256 threads, 8x8 micro-tile.
// Inner product uses packed fma.rn.f32x2 (2 MACs per instruction).
// ---------------------------------------------------------------------------
template<int K>
__global__ __launch_bounds__(256) void gemm_bias_relu(
    const float* __restrict__ A, const float* __restrict__ B,
    const float* __restrict__ bias, float* __restrict__ C,
    int M, int col0)
{
    constexpr int BM = 128, BN = 128, BK = 16;
    __shared__ __align__(16) float As[BK][BM];   // transposed A tile
    __shared__ __align__(16) float Bs[BK][BN];

    const int tid = threadIdx.x;
    const int tx = tid & 15;        // output column group
    const int ty = tid >> 4;        // output row group
    const int m0 = blockIdx.x * BM;

    // Accumulators: 8 rows x 4 f32x2 pairs (= 8 columns)
    unsigned long long acc2[8][4];
    #pragma unroll
    for (int i = 0; i < 8; i++)
        #pragma unroll
        for (int j = 0; j < 4; j++)
            acc2[i][j] = 0ULL;      // two packed 0.0f

    for (int k0 = 0; k0 < K; k0 += BK) {
        // Load A tile (128 x 16) -> As transposed. 512 float4 slots / 256 thr.
        #pragma unroll
        for (int it = 0; it < 2; it++) {
            int idx = tid + it * 256;
            int row = idx >> 2;            // 0..127
            int c4  = (idx & 3) * 4;       // 0,4,8,12
            int m = m0 + row;
            float4 v = make_float4(0.f, 0.f, 0.f, 0.f);
            if (m < M)
                v = *reinterpret_cast<const float4*>(A + (long long)m * K + k0 + c4);
            As[c4 + 0][row] = v.x;
            As[c4 + 1][row] = v.y;
            As[c4 + 2][row] = v.z;
            As[c4 + 3][row] = v.w;
        }
        // Load B tile (16 x 128). 512 float4 slots / 256 thr.
        #pragma unroll
        for (int it = 0; it < 2; it++) {
            int idx = tid + it * 256;
            int row = idx >> 5;            // 0..15
            int c4  = (idx & 31) * 4;      // 0..124
            *reinterpret_cast<float4*>(&Bs[row][c4]) =
                *reinterpret_cast<const float4*>(B + (long long)(k0 + row) * BN + c4);
        }
        __syncthreads();

        #pragma unroll
        for (int k = 0; k < BK; k++) {
            float ra[8];
            *reinterpret_cast<float4*>(&ra[0]) =
                *reinterpret_cast<const float4*>(&As[k][ty * 8]);
            *reinterpret_cast<float4*>(&ra[4]) =
                *reinterpret_cast<const float4*>(&As[k][ty * 8 + 4]);

            unsigned long long b2[4];
            {
                const ulonglong2* bp =
                    reinterpret_cast<const ulonglong2*>(&Bs[k][tx * 8]);
                ulonglong2 t0 = bp[0];
                ulonglong2 t1 = bp[1];
                b2[0] = t0.x; b2[1] = t0.y; b2[2] = t1.x; b2[3] = t1.y;
            }

            #pragma unroll
            for (int i = 0; i < 8; i++) {
                unsigned long long a2;
                asm("mov.b64 %0, {%1, %1};" : "=l"(a2) : "f"(ra[i]));
                #pragma unroll
                for (int jj = 0; jj < 4; jj++)
                    asm("fma.rn.f32x2 %0, %1, %2, %0;"
                        : "+l"(acc2[i][jj]) : "l"(a2), "l"(b2[jj]));
            }
        }
        __syncthreads();
    }

    // Epilogue: unpack, bias + relu, float4 stores into the proper half of out.
    #pragma unroll
    for (int i = 0; i < 8; i++) {
        int m = m0 + ty * 8 + i;
        if (m >= M) continue;
        #pragma unroll
        for (int jj = 0; jj < 4; jj += 2) {
            int c = tx * 8 + jj * 2;
            float v0, v1, v2, v3;
            asm("mov.b64 {%0, %1}, %2;" : "=f"(v0), "=f"(v1) : "l"(acc2[i][jj]));
            asm("mov.b64 {%0, %1}, %2;" : "=f"(v2), "=f"(v3) : "l"(acc2[i][jj + 1]));
            float4 o;
            o.x = fmaxf(v0 + bias[c + 0], 0.f);
            o.y = fmaxf(v1 + bias[c + 1], 0.f);
            o.z = fmaxf(v2 + bias[c + 2], 0.f);
            o.w = fmaxf(v3 + bias[c + 3], 0.f);
            *reinterpret_cast<float4*>(C + (long long)m * OW + col0 + c) = o;
        }
    }
}

extern "C" void kernel_launch(void* const* d_in, const int* in_sizes, int n_in,
                              void* d_out, int out_size) {
    const float* x    = (const float*)d_in[0];
    const void*  eidx = d_in[1];                 // [2, E]; dtype detected on device
    const float* ea   = (const float*)d_in[2];
    const float* Wx   = (const float*)d_in[3];
    const float* bx   = (const float*)d_in[4];
    const float* We   = (const float*)d_in[5];
    const float* be   = (const float*)d_in[6];
    float*       out  = (float*)d_out;

    const int N = in_sizes[0] / FX;
    const int E = in_sizes[2] / FE;

    float* agg_ptr = nullptr;
    cudaGetSymbolAddress((void**)&agg_ptr, g_agg);

    // 0) detect index dtype (int32 vs int64)
    detect_kernel<<<1, 256>>>((const long long*)eidx, E, N);

    // 1) zero agg scratch
    int n4 = N * FE / 4;
    zero_agg_kernel<<<(n4 + 255) / 256, 256>>>(n4);

    // 2) scatter-add edge features (vector RED)
    int E8 = E * 8;
    scatter_kernel<<<(E8 + 255) / 256, 256>>>(
        reinterpret_cast<const float4*>(ea), eidx, E8, N);

    // 3) hx = relu(x @ Wx + bx) -> out[:, 0:128]
    int gb = (N + 127) / 128;
    gemm_bias_relu<FX><<<gb, 256>>>(x, Wx, bx, out, N, 0);

    // 4) he = relu(agg @ We + be) -> out[:, 128:256]
    gemm_bias_relu<FE><<<gb, 256>>>(agg_ptr, We, be, out, N, 128);
}

// round 5
// speedup vs baseline: 1.8997x; 1.4901x over previous
#include <cuda_runtime.h>

// Problem constants (fixed for this dataset)
#define FX 128   // node feature dim / OX
#define FE 32    // edge feature dim
#define OW 256   // output row width (128 + 128)
#define MAXN 100000

// Static device scratch (no allocation allowed).
__device__ __align__(16) float g_agg[MAXN * FE];    // segment-sum result [N, FE]
__device__ __align__(16) float g_WxT[FX * FX];      // Wx transposed: [n=128][k=128]
__device__ __align__(16) float g_WeT[FX * FE];      // We transposed: [n=128][k=32]
__device__ int g_idx_is64;

__device__ __forceinline__ float cvt_tf32(float x) {
    // Round-to-nearest tf32 (truncation would bias the K-sum).
    unsigned r;
    asm("cvt.rna.tf32.f32 %0, %1;" : "=r"(r) : "f"(x));
    return __uint_as_float(r);
}

// ===========================================================================
// Small prep kernels
// ===========================================================================
__global__ void detect_kernel(const long long* __restrict__ idx64, int E, int N) {
    __shared__ int bad;
    if (threadIdx.x == 0) bad = 0;
    __syncthreads();
    int n = E < 4096 ? E : 4096;
    for (int i = threadIdx.x; i < n; i += blockDim.x) {
        long long v = idx64[i];
        if (v < 0 || v >= (long long)N) bad = 1;
    }
    __syncthreads();
    if (threadIdx.x == 0) g_idx_is64 = bad ? 0 : 1;
}

__global__ void zero_agg_kernel(int n4) {
    int i = blockIdx.x * blockDim.x + threadIdx.x;
    if (i < n4)
        reinterpret_cast<float4*>(g_agg)[i] = make_float4(0.f, 0.f, 0.f, 0.f);
}

// Transpose both weight matrices into K-major [N, K] layout for the MMA.
__global__ void transpose_B(const float* __restrict__ Wx, const float* __restrict__ We) {
    int i = blockIdx.x * blockDim.x + threadIdx.x;
    if (i < FX * FX) {                    // WxT[n][k] = Wx[k][n], Wx is [128,128]
        int n = i / FX, k = i % FX;
        g_WxT[n * FX + k] = Wx[k * FX + n];
    }
    if (i < FX * FE) {                    // WeT[n][k] = We[k][n], We is [32,128]
        int n = i / FE, k = i % FE;
        g_WeT[n * FE + k] = We[k * FX + n];
    }
}

// ===========================================================================
// Scatter-add: agg[row[e], :] += edge_attr[e, :]  (v4 RED, 1 instr / 16B)
// ===========================================================================
__global__ void scatter_kernel(const float4* __restrict__ ea,
                               const void* __restrict__ row_idx,
                               int E8, int N) {
    int tid = blockIdx.x * blockDim.x + threadIdx.x;
    if (tid >= E8) return;
    float4 v = ea[tid];
    int e = tid >> 3;
    int q = tid & 7;
    long long r;
    if (g_idx_is64)
        r = ((const long long*)row_idx)[e];
    else
        r = (long long)((const int*)row_idx)[e];
    if (r < 0 || r >= (long long)N) return;
    float* dst = g_agg + r * FE + q * 4;
    asm volatile("red.global.add.v4.f32 [%0], {%1, %2, %3, %4};"
                 :: "l"(dst), "f"(v.x), "f"(v.y), "f"(v.z), "f"(v.w)
                 : "memory");
}

// ===========================================================================
// Tensor-core GEMM via mma.sync.m16n8k8.tf32 (family-common PTX, HMMA SASS).
// C[m, col0+n] = relu(sum_k A[m,k] * Bt[n,k] + bias[n]),  n in [0,128)
// CTA: 256 thr = 8 warps in a 4(M) x 2(N) grid; warp tile 32x64.
// Per warp: 2 m16 frags x 8 n8 frags, K consumed in chunks of 32 via smem.
// ===========================================================================
template<int K>
__global__ __launch_bounds__(256) void gemm_mma(
    const float* __restrict__ A, const float* __restrict__ Bt,
    const float* __restrict__ bias, float* __restrict__ C,
    int M, int col0)
{
    constexpr int BK = 32;
    constexpr int NCHUNK = K / BK;
    constexpr int LDS = BK + 4;            // padded row stride (floats)
    __shared__ __align__(16) float As[128][LDS];
    __shared__ __align__(16) float Bs[128][LDS];

    const int tid  = threadIdx.x;
    const int wid  = tid >> 5;
    const int lane = tid & 31;
    const int g = lane >> 2;               // group id 0..7
    const int t = lane & 3;                // thread in group 0..3
    const int wm0 = (wid & 3) * 32;        // warp row offset in tile
    const int wn0 = (wid >> 2) * 64;       // warp col offset in tile
    const int m0 = blockIdx.x * 128;

    float acc[2][8][4];
    #pragma unroll
    for (int mf = 0; mf < 2; mf++)
        #pragma unroll
        for (int nf = 0; nf < 8; nf++)
            #pragma unroll
            for (int c = 0; c < 4; c++)
                acc[mf][nf][c] = 0.f;

    for (int ch = 0; ch < NCHUNK; ch++) {
        const int k0 = ch * BK;
        // ---- Load A chunk: 128 rows x 32 cols = 1024 float4, 4 per thread.
        #pragma unroll
        for (int i = 0; i < 4; i++) {
            int idx = tid + i * 256;
            int row = idx >> 3;
            int c4  = (idx & 7) * 4;
            int m = m0 + row;
            float4 v = make_float4(0.f, 0.f, 0.f, 0.f);
            if (m < M)
                v = *reinterpret_cast<const float4*>(A + (long long)m * K + k0 + c4);
            v.x = cvt_tf32(v.x); v.y = cvt_tf32(v.y);
            v.z = cvt_tf32(v.z); v.w = cvt_tf32(v.w);
            *reinterpret_cast<float4*>(&As[row][c4]) = v;
        }
        // ---- Load B chunk: Bt[n][k0..k0+32), same shape.
        #pragma unroll
        for (int i = 0; i < 4; i++) {
            int idx = tid + i * 256;
            int row = idx >> 3;
            int c4  = (idx & 7) * 4;
            float4 v = *reinterpret_cast<const float4*>(Bt + (long long)row * K + k0 + c4);
            v.x = cvt_tf32(v.x); v.y = cvt_tf32(v.y);
            v.z = cvt_tf32(v.z); v.w = cvt_tf32(v.w);
            *reinterpret_cast<float4*>(&Bs[row][c4]) = v;
        }
        __syncthreads();

        #pragma unroll
        for (int kk = 0; kk < BK / 8; kk++) {
            const int kb = kk * 8;
            // B fragments: b0 = B[k=t][n=g] -> Bs[n][k]
            unsigned bf[8][2];
            #pragma unroll
            for (int nf = 0; nf < 8; nf++) {
                bf[nf][0] = __float_as_uint(Bs[wn0 + nf * 8 + g][kb + t]);
                bf[nf][1] = __float_as_uint(Bs[wn0 + nf * 8 + g][kb + t + 4]);
            }
            #pragma unroll
            for (int mf = 0; mf < 2; mf++) {
                const int ar = wm0 + mf * 16 + g;
                unsigned a0 = __float_as_uint(As[ar    ][kb + t]);
                unsigned a1 = __float_as_uint(As[ar + 8][kb + t]);
                unsigned a2 = __float_as_uint(As[ar    ][kb + t + 4]);
                unsigned a3 = __float_as_uint(As[ar + 8][kb + t + 4]);
                #pragma unroll
                for (int nf = 0; nf < 8; nf++) {
                    asm volatile(
                        "mma.sync.aligned.m16n8k8.row.col.f32.tf32.tf32.f32 "
                        "{%0,%1,%2,%3}, {%4,%5,%6,%7}, {%8,%9}, {%0,%1,%2,%3};"
                        : "+f"(acc[mf][nf][0]), "+f"(acc[mf][nf][1]),
                          "+f"(acc[mf][nf][2]), "+f"(acc[mf][nf][3])
                        : "r"(a0), "r"(a1), "r"(a2), "r"(a3),
                          "r"(bf[nf][0]), "r"(bf[nf][1]));
                }
            }
        }
        __syncthreads();
    }

    // ---- Epilogue: bias + relu, float2 stores.
    // c0,c1 -> row g, cols 2t,2t+1 ; c2,c3 -> row g+8.
    #pragma unroll
    for (int mf = 0; mf < 2; mf++) {
        #pragma unroll
        for (int rr = 0; rr < 2; rr++) {
            int m = m0 + wm0 + mf * 16 + g + rr * 8;
            if (m >= M) continue;
            float* dst = C + (long long)m * OW + col0 + wn0;
            #pragma unroll
            for (int nf = 0; nf < 8; nf++) {
                int c = nf * 8 + 2 * t;
                float2 bb = *reinterpret_cast<const float2*>(bias + wn0 + c);
                float2 o;
                o.x = fmaxf(acc[mf][nf][rr * 2 + 0] + bb.x, 0.f);
                o.y = fmaxf(acc[mf][nf][rr * 2 + 1] + bb.y, 0.f);
                *reinterpret_cast<float2*>(dst + c) = o;
            }
        }
    }
}

// ===========================================================================
extern "C" void kernel_launch(void* const* d_in, const int* in_sizes, int n_in,
                              void* d_out, int out_size) {
    const float* x    = (const float*)d_in[0];
    const void*  eidx = d_in[1];                 // [2, E]; dtype detected on device
    const float* ea   = (const float*)d_in[2];
    const float* Wx   = (const float*)d_in[3];
    const float* bx   = (const float*)d_in[4];
    const float* We   = (const float*)d_in[5];
    const float* be   = (const float*)d_in[6];
    float*       out  = (float*)d_out;

    const int N = in_sizes[0] / FX;
    const int E = in_sizes[2] / FE;

    float *agg_ptr = nullptr, *wxt_ptr = nullptr, *wet_ptr = nullptr;
    cudaGetSymbolAddress((void**)&agg_ptr, g_agg);
    cudaGetSymbolAddress((void**)&wxt_ptr, g_WxT);
    cudaGetSymbolAddress((void**)&wet_ptr, g_WeT);

    // 0) detect index dtype; transpose weights; zero agg
    detect_kernel<<<1, 256>>>((const long long*)eidx, E, N);
    transpose_B<<<(FX * FX + 255) / 256, 256>>>(Wx, We);
    int n4 = N * FE / 4;
    zero_agg_kernel<<<(n4 + 255) / 256, 256>>>(n4);

    // 1) scatter-add edge features (vector RED)
    int E8 = E * 8;
    scatter_kernel<<<(E8 + 255) / 256, 256>>>(
        reinterpret_cast<const float4*>(ea), eidx, E8, N);

    // 2) hx = relu(x @ Wx + bx) -> out[:, 0:128]   (HMMA tf32)
    int gb = (N + 127) / 128;
    gemm_mma<FX><<<gb, 256>>>(x, wxt_ptr, bx, out, N, 0);

    // 3) he = relu(agg @ We + be) -> out[:, 128:256]
    gemm_mma<FE><<<gb, 256>>>(agg_ptr, wet_ptr, be, out, N, 128);
}

// round 7
// speedup vs baseline: 2.1601x; 1.1370x over previous
#include <cuda_runtime.h>

// Problem constants (fixed for this dataset)
#define FX 128   // node feature dim / OX
#define FE 32    // edge feature dim
#define OW 256   // output row width (128 + 128)
#define MAXN 100000

// Static device scratch (no allocation allowed).
__device__ __align__(16) float g_agg[MAXN * FE];    // segment-sum result [N, FE]
__device__ __align__(16) float g_WxT[FX * FX];      // Wx transposed: [n=128][k=128]
__device__ __align__(16) float g_WeT[FX * FE];      // We transposed: [n=128][k=32]
__device__ int g_idx_is64;

__device__ __forceinline__ float cvt_tf32(float x) {
    unsigned r;
    asm("cvt.rna.tf32.f32 %0, %1;" : "=r"(r) : "f"(x));
    return __uint_as_float(r);
}

// ===========================================================================
// Fused prep: block 0 = index-dtype detect; blocks 1..16 = Wx transpose tiles;
// blocks 17..20 = We transpose tiles; blocks 21.. = zero g_agg.
// ===========================================================================
#define PREP_FIXED 21
__global__ void prep_kernel(const long long* __restrict__ idx64,
                            const float* __restrict__ Wx,
                            const float* __restrict__ We,
                            int E, int N, int n4) {
    const int b = blockIdx.x;
    const int t = threadIdx.x;

    if (b == 0) {
        // ---- detect int64 vs int32 edge_index
        __shared__ int bad;
        if (t == 0) bad = 0;
        __syncthreads();
        int n = E < 4096 ? E : 4096;
        for (int i = t; i < n; i += blockDim.x) {
            long long v = idx64[i];
            if (v < 0 || v >= (long long)N) bad = 1;
        }
        __syncthreads();
        if (t == 0) g_idx_is64 = bad ? 0 : 1;
        return;
    }
    if (b <= 20) {
        // ---- coalesced 32x32 smem transpose tiles
        __shared__ float tile[32][33];
        const int tx = t & 31;
        const int ty = t >> 5;          // 0..7
        if (b <= 16) {                  // Wx [128k x 128n] -> WxT[n][k]
            int ti = b - 1;
            int tk = (ti >> 2) * 32, tn = (ti & 3) * 32;
            #pragma unroll
            for (int r = 0; r < 4; r++) {
                int row = ty + r * 8;
                tile[row][tx] = Wx[(tk + row) * FX + tn + tx];
            }
            __syncthreads();
            #pragma unroll
            for (int r = 0; r < 4; r++) {
                int row = ty + r * 8;
                g_WxT[(tn + row) * FX + tk + tx] = tile[tx][row];
            }
        } else {                        // We [32k x 128n] -> WeT[n][k]
            int tn = (b - 17) * 32;
            #pragma unroll
            for (int r = 0; r < 4; r++) {
                int row = ty + r * 8;
                tile[row][tx] = We[row * FX + tn + tx];
            }
            __syncthreads();
            #pragma unroll
            for (int r = 0; r < 4; r++) {
                int row = ty + r * 8;
                g_WeT[(tn + row) * FE + tx] = tile[tx][row];
            }
        }
        return;
    }
    // ---- zero g_agg
    int i = (b - PREP_FIXED) * blockDim.x + t;
    if (i < n4)
        reinterpret_cast<float4*>(g_agg)[i] = make_float4(0.f, 0.f, 0.f, 0.f);
}

// ===========================================================================
// Scatter-add: agg[row[e], :] += edge_attr[e, :]  (v4 RED, 1 instr / 16B)
// ===========================================================================
__global__ void scatter_kernel(const float4* __restrict__ ea,
                               const void* __restrict__ row_idx,
                               int E8, int N) {
    int tid = blockIdx.x * blockDim.x + threadIdx.x;
    if (tid >= E8) return;
    float4 v = ea[tid];
    int e = tid >> 3;
    int q = tid & 7;
    long long r;
    if (g_idx_is64)
        r = ((const long long*)row_idx)[e];
    else
        r = (long long)((const int*)row_idx)[e];
    if (r < 0 || r >= (long long)N) return;
    float* dst = g_agg + r * FE + q * 4;
    asm volatile("red.global.add.v4.f32 [%0], {%1, %2, %3, %4};"
                 :: "l"(dst), "f"(v.x), "f"(v.y), "f"(v.z), "f"(v.w)
                 : "memory");
}

// ===========================================================================
// Tensor-core GEMM via mma.sync.m16n8k8.tf32 (family-common PTX).
// C[m, col0+n] = relu(sum_k A[m,k] * Bt[n,k] + bias[n]),  n in [0,128)
// ===========================================================================
template<int K>
__global__ __launch_bounds__(256) void gemm_mma(
    const float* __restrict__ A, const float* __restrict__ Bt,
    const float* __restrict__ bias, float* __restrict__ C,
    int M, int col0)
{
    constexpr int BK = 32;
    constexpr int NCHUNK = K / BK;
    constexpr int LDS = BK + 4;
    __shared__ __align__(16) float As[128][LDS];
    __shared__ __align__(16) float Bs[128][LDS];

    const int tid  = threadIdx.x;
    const int wid  = tid >> 5;
    const int lane = tid & 31;
    const int g = lane >> 2;
    const int t = lane & 3;
    const int wm0 = (wid & 3) * 32;
    const int wn0 = (wid >> 2) * 64;
    const int m0 = blockIdx.x * 128;

    float acc[2][8][4];
    #pragma unroll
    for (int mf = 0; mf < 2; mf++)
        #pragma unroll
        for (int nf = 0; nf < 8; nf++)
            #pragma unroll
            for (int c = 0; c < 4; c++)
                acc[mf][nf][c] = 0.f;

    for (int ch = 0; ch < NCHUNK; ch++) {
        const int k0 = ch * BK;
        #pragma unroll
        for (int i = 0; i < 4; i++) {
            int idx = tid + i * 256;
            int row = idx >> 3;
            int c4  = (idx & 7) * 4;
            int m = m0 + row;
            float4 v = make_float4(0.f, 0.f, 0.f, 0.f);
            if (m < M)
                v = *reinterpret_cast<const float4*>(A + (long long)m * K + k0 + c4);
            v.x = cvt_tf32(v.x); v.y = cvt_tf32(v.y);
            v.z = cvt_tf32(v.z); v.w = cvt_tf32(v.w);
            *reinterpret_cast<float4*>(&As[row][c4]) = v;
        }
        #pragma unroll
        for (int i = 0; i < 4; i++) {
            int idx = tid + i * 256;
            int row = idx >> 3;
            int c4  = (idx & 7) * 4;
            float4 v = *reinterpret_cast<const float4*>(Bt + (long long)row * K + k0 + c4);
            v.x = cvt_tf32(v.x); v.y = cvt_tf32(v.y);
            v.z = cvt_tf32(v.z); v.w = cvt_tf32(v.w);
            *reinterpret_cast<float4*>(&Bs[row][c4]) = v;
        }
        __syncthreads();

        #pragma unroll
        for (int kk = 0; kk < BK / 8; kk++) {
            const int kb = kk * 8;
            unsigned bf[8][2];
            #pragma unroll
            for (int nf = 0; nf < 8; nf++) {
                bf[nf][0] = __float_as_uint(Bs[wn0 + nf * 8 + g][kb + t]);
                bf[nf][1] = __float_as_uint(Bs[wn0 + nf * 8 + g][kb + t + 4]);
            }
            #pragma unroll
            for (int mf = 0; mf < 2; mf++) {
                const int ar = wm0 + mf * 16 + g;
                unsigned a0 = __float_as_uint(As[ar    ][kb + t]);
                unsigned a1 = __float_as_uint(As[ar + 8][kb + t]);
                unsigned a2 = __float_as_uint(As[ar    ][kb + t + 4]);
                unsigned a3 = __float_as_uint(As[ar + 8][kb + t + 4]);
                #pragma unroll
                for (int nf = 0; nf < 8; nf++) {
                    asm volatile(
                        "mma.sync.aligned.m16n8k8.row.col.f32.tf32.tf32.f32 "
                        "{%0,%1,%2,%3}, {%4,%5,%6,%7}, {%8,%9}, {%0,%1,%2,%3};"
                        : "+f"(acc[mf][nf][0]), "+f"(acc[mf][nf][1]),
                          "+f"(acc[mf][nf][2]), "+f"(acc[mf][nf][3])
                        : "r"(a0), "r"(a1), "r"(a2), "r"(a3),
                          "r"(bf[nf][0]), "r"(bf[nf][1]));
                }
            }
        }
        __syncthreads();
    }

    #pragma unroll
    for (int mf = 0; mf < 2; mf++) {
        #pragma unroll
        for (int rr = 0; rr < 2; rr++) {
            int m = m0 + wm0 + mf * 16 + g + rr * 8;
            if (m >= M) continue;
            float* dst = C + (long long)m * OW + col0 + wn0;
            #pragma unroll
            for (int nf = 0; nf < 8; nf++) {
                int c = nf * 8 + 2 * t;
                float2 bb = *reinterpret_cast<const float2*>(bias + wn0 + c);
                float2 o;
                o.x = fmaxf(acc[mf][nf][rr * 2 + 0] + bb.x, 0.f);
                o.y = fmaxf(acc[mf][nf][rr * 2 + 1] + bb.y, 0.f);
                *reinterpret_cast<float2*>(dst + c) = o;
            }
        }
    }
}

// ===========================================================================
extern "C" void kernel_launch(void* const* d_in, const int* in_sizes, int n_in,
                              void* d_out, int out_size) {
    const float* x    = (const float*)d_in[0];
    const void*  eidx = d_in[1];
    const float* ea   = (const float*)d_in[2];
    const float* Wx   = (const float*)d_in[3];
    const float* bx   = (const float*)d_in[4];
    const float* We   = (const float*)d_in[5];
    const float* be   = (const float*)d_in[6];
    float*       out  = (float*)d_out;

    const int N = in_sizes[0] / FX;
    const int E = in_sizes[2] / FE;

    float *agg_ptr = nullptr, *wxt_ptr = nullptr, *wet_ptr = nullptr;
    cudaGetSymbolAddress((void**)&agg_ptr, g_agg);
    cudaGetSymbolAddress((void**)&wxt_ptr, g_WxT);
    cudaGetSymbolAddress((void**)&wet_ptr, g_WeT);

    // Lazy one-time creation of side stream + events (first call is the
    // non-captured correctness run; capture call reuses them).
    static cudaStream_t s_side = nullptr;
    static cudaEvent_t  s_fork = nullptr, s_join = nullptr;
    static bool s_tried = false;
    if (!s_tried) {
        s_tried = true;
        if (cudaStreamCreateWithFlags(&s_side, cudaStreamNonBlocking) != cudaSuccess)
            s_side = nullptr;
        if (s_side) {
            if (cudaEventCreateWithFlags(&s_fork, cudaEventDisableTiming) != cudaSuccess ||
                cudaEventCreateWithFlags(&s_join, cudaEventDisableTiming) != cudaSuccess)
                s_side = nullptr;
        }
    }

    // 0) fused prep: detect + transpose weights + zero agg
    int n4 = N * FE / 4;
    int prep_blocks = PREP_FIXED + (n4 + 255) / 256;
    prep_kernel<<<prep_blocks, 256>>>((const long long*)eidx, Wx, We, E, N, n4);

    int gb = (N + 127) / 128;
    int E8 = E * 8;

    if (s_side) {
        // fork: gemm128 runs concurrently with the scatter chain
        cudaEventRecord(s_fork, 0);
        cudaStreamWaitEvent(s_side, s_fork, 0);
        gemm_mma<FX><<<gb, 256, 0, s_side>>>(x, wxt_ptr, bx, out, N, 0);
        cudaEventRecord(s_join, s_side);

        scatter_kernel<<<(E8 + 255) / 256, 256>>>(
            reinterpret_cast<const float4*>(ea), eidx, E8, N);
        gemm_mma<FE><<<gb, 256>>>(agg_ptr, wet_ptr, be, out, N, 128);

        cudaStreamWaitEvent(0, s_join, 0);   // join before returning
    } else {
        // fallback: fully serial (round-5 behavior)
        scatter_kernel<<<(E8 + 255) / 256, 256>>>(
            reinterpret_cast<const float4*>(ea), eidx, E8, N);
        gemm_mma<FX><<<gb, 256>>>(x, wxt_ptr, bx, out, N, 0);
        gemm_mma<FE><<<gb, 256>>>(agg_ptr, wet_ptr, be, out, N, 128);
    }
}

// round 8
// speedup vs baseline: 2.1758x; 1.0073x over previous
#include <cuda_runtime.h>

// Problem constants (fixed for this dataset)
#define FX 128   // node feature dim / OX
#define FE 32    // edge feature dim
#define OW 256   // output row width (128 + 128)
#define MAXN 100000

// Static device scratch (no allocation allowed).
__device__ __align__(16) float g_agg[MAXN * FE];    // segment-sum result [N, FE]
__device__ __align__(16) float g_WxT[FX * FX];      // Wx transposed: [n=128][k=128]
__device__ __align__(16) float g_WeT[FX * FE];      // We transposed: [n=128][k=32]
__device__ int g_idx_is64;

__device__ __forceinline__ float cvt_tf32(float x) {
    unsigned r;
    asm("cvt.rna.tf32.f32 %0, %1;" : "=r"(r) : "f"(x));
    return __uint_as_float(r);
}

// ===========================================================================
// Fused prep: block 0 = index-dtype detect; blocks 1..16 = Wx transpose tiles;
// blocks 17..20 = We transpose tiles; blocks 21.. = zero g_agg.
// ===========================================================================
#define PREP_FIXED 21
__global__ void prep_kernel(const long long* __restrict__ idx64,
                            const float* __restrict__ Wx,
                            const float* __restrict__ We,
                            int E, int N, int n4) {
    const int b = blockIdx.x;
    const int t = threadIdx.x;

    if (b == 0) {
        __shared__ int bad;
        if (t == 0) bad = 0;
        __syncthreads();
        int n = E < 4096 ? E : 4096;
        for (int i = t; i < n; i += blockDim.x) {
            long long v = idx64[i];
            if (v < 0 || v >= (long long)N) bad = 1;
        }
        __syncthreads();
        if (t == 0) g_idx_is64 = bad ? 0 : 1;
        return;
    }
    if (b <= 20) {
        __shared__ float tile[32][33];
        const int tx = t & 31;
        const int ty = t >> 5;          // 0..7
        if (b <= 16) {                  // Wx [128k x 128n] -> WxT[n][k]
            int ti = b - 1;
            int tk = (ti >> 2) * 32, tn = (ti & 3) * 32;
            #pragma unroll
            for (int r = 0; r < 4; r++) {
                int row = ty + r * 8;
                tile[row][tx] = Wx[(tk + row) * FX + tn + tx];
            }
            __syncthreads();
            #pragma unroll
            for (int r = 0; r < 4; r++) {
                int row = ty + r * 8;
                g_WxT[(tn + row) * FX + tk + tx] = tile[tx][row];
            }
        } else {                        // We [32k x 128n] -> WeT[n][k]
            int tn = (b - 17) * 32;
            #pragma unroll
            for (int r = 0; r < 4; r++) {
                int row = ty + r * 8;
                tile[row][tx] = We[row * FX + tn + tx];
            }
            __syncthreads();
            #pragma unroll
            for (int r = 0; r < 4; r++) {
                int row = ty + r * 8;
                g_WeT[(tn + row) * FE + tx] = tile[tx][row];
            }
        }
        return;
    }
    int i = (b - PREP_FIXED) * blockDim.x + t;
    if (i < n4)
        reinterpret_cast<float4*>(g_agg)[i] = make_float4(0.f, 0.f, 0.f, 0.f);
}

// ===========================================================================
// Scatter-add: agg[row[e], :] += edge_attr[e, :]  (v4 RED, 1 instr / 16B)
// ===========================================================================
__global__ void scatter_kernel(const float4* __restrict__ ea,
                               const void* __restrict__ row_idx,
                               int E8, int N) {
    int tid = blockIdx.x * blockDim.x + threadIdx.x;
    if (tid >= E8) return;
    float4 v = ea[tid];
    int e = tid >> 3;
    int q = tid & 7;
    long long r;
    if (g_idx_is64)
        r = ((const long long*)row_idx)[e];
    else
        r = (long long)((const int*)row_idx)[e];
    if (r < 0 || r >= (long long)N) return;
    float* dst = g_agg + r * FE + q * 4;
    asm volatile("red.global.add.v4.f32 [%0], {%1, %2, %3, %4};"
                 :: "l"(dst), "f"(v.x), "f"(v.y), "f"(v.z), "f"(v.w)
                 : "memory");
}

// ===========================================================================
// Tensor-core GEMM via mma.sync.m16n8k8.tf32 (family-common PTX).
// C[m, colbase+n] = relu(sum_k A[m,k] * Bt[n,k] + bias[colbase+n])
// CTA tile: 128(M) x BN(N); 256 thr = 8 warps as 4(M) x 2(N);
// warp tile 32 x BN/2. gridDim.y slices N into BN chunks.
// ===========================================================================
template<int K, int BN>
__global__ __launch_bounds__(256) void gemm_mma(
    const float* __restrict__ A, const float* __restrict__ Bt,
    const float* __restrict__ bias, float* __restrict__ C,
    int M, int col0)
{
    constexpr int BK = 32;
    constexpr int NCHUNK = K / BK;
    constexpr int NFC = BN / 16;           // n-fragments per warp
    constexpr int LDS = BK + 4;
    __shared__ __align__(16) float As[128][LDS];
    __shared__ __align__(16) float Bs[BN][LDS];

    const int tid  = threadIdx.x;
    const int wid  = tid >> 5;
    const int lane = tid & 31;
    const int g = lane >> 2;
    const int t = lane & 3;
    const int wm0 = (wid & 3) * 32;
    const int wn0 = (wid >> 2) * (BN / 2);
    const int m0 = blockIdx.x * 128;
    const int nb0 = blockIdx.y * BN;       // N-slice base

    float acc[2][NFC][4];
    #pragma unroll
    for (int mf = 0; mf < 2; mf++)
        #pragma unroll
        for (int nf = 0; nf < NFC; nf++)
            #pragma unroll
            for (int c = 0; c < 4; c++)
                acc[mf][nf][c] = 0.f;

    for (int ch = 0; ch < NCHUNK; ch++) {
        const int k0 = ch * BK;
        // A chunk: 128 rows x 32 cols = 1024 float4, 4/thread.
        #pragma unroll
        for (int i = 0; i < 4; i++) {
            int idx = tid + i * 256;
            int row = idx >> 3;
            int c4  = (idx & 7) * 4;
            int m = m0 + row;
            float4 v = make_float4(0.f, 0.f, 0.f, 0.f);
            if (m < M)
                v = *reinterpret_cast<const float4*>(A + (long long)m * K + k0 + c4);
            v.x = cvt_tf32(v.x); v.y = cvt_tf32(v.y);
            v.z = cvt_tf32(v.z); v.w = cvt_tf32(v.w);
            *reinterpret_cast<float4*>(&As[row][c4]) = v;
        }
        // B chunk: BN rows x 32 cols.
        #pragma unroll
        for (int i = 0; i < BN / 32; i++) {
            int idx = tid + i * 256;
            int row = idx >> 3;
            int c4  = (idx & 7) * 4;
            float4 v = *reinterpret_cast<const float4*>(
                Bt + (long long)(nb0 + row) * K + k0 + c4);
            v.x = cvt_tf32(v.x); v.y = cvt_tf32(v.y);
            v.z = cvt_tf32(v.z); v.w = cvt_tf32(v.w);
            *reinterpret_cast<float4*>(&Bs[row][c4]) = v;
        }
        __syncthreads();

        #pragma unroll
        for (int kk = 0; kk < BK / 8; kk++) {
            const int kb = kk * 8;
            unsigned bf[NFC][2];
            #pragma unroll
            for (int nf = 0; nf < NFC; nf++) {
                bf[nf][0] = __float_as_uint(Bs[wn0 + nf * 8 + g][kb + t]);
                bf[nf][1] = __float_as_uint(Bs[wn0 + nf * 8 + g][kb + t + 4]);
            }
            #pragma unroll
            for (int mf = 0; mf < 2; mf++) {
                const int ar = wm0 + mf * 16 + g;
                unsigned a0 = __float_as_uint(As[ar    ][kb + t]);
                unsigned a1 = __float_as_uint(As[ar + 8][kb + t]);
                unsigned a2 = __float_as_uint(As[ar    ][kb + t + 4]);
                unsigned a3 = __float_as_uint(As[ar + 8][kb + t + 4]);
                #pragma unroll
                for (int nf = 0; nf < NFC; nf++) {
                    asm volatile(
                        "mma.sync.aligned.m16n8k8.row.col.f32.tf32.tf32.f32 "
                        "{%0,%1,%2,%3}, {%4,%5,%6,%7}, {%8,%9}, {%0,%1,%2,%3};"
                        : "+f"(acc[mf][nf][0]), "+f"(acc[mf][nf][1]),
                          "+f"(acc[mf][nf][2]), "+f"(acc[mf][nf][3])
                        : "r"(a0), "r"(a1), "r"(a2), "r"(a3),
                          "r"(bf[nf][0]), "r"(bf[nf][1]));
                }
            }
        }
        __syncthreads();
    }

    #pragma unroll
    for (int mf = 0; mf < 2; mf++) {
        #pragma unroll
        for (int rr = 0; rr < 2; rr++) {
            int m = m0 + wm0 + mf * 16 + g + rr * 8;
            if (m >= M) continue;
            float* dst = C + (long long)m * OW + col0 + nb0 + wn0;
            const float* bp = bias + nb0 + wn0;
            #pragma unroll
            for (int nf = 0; nf < NFC; nf++) {
                int c = nf * 8 + 2 * t;
                float2 bb = *reinterpret_cast<const float2*>(bp + c);
                float2 o;
                o.x = fmaxf(acc[mf][nf][rr * 2 + 0] + bb.x, 0.f);
                o.y = fmaxf(acc[mf][nf][rr * 2 + 1] + bb.y, 0.f);
                *reinterpret_cast<float2*>(dst + c) = o;
            }
        }
    }
}

// ===========================================================================
extern "C" void kernel_launch(void* const* d_in, const int* in_sizes, int n_in,
                              void* d_out, int out_size) {
    const float* x    = (const float*)d_in[0];
    const void*  eidx = d_in[1];
    const float* ea   = (const float*)d_in[2];
    const float* Wx   = (const float*)d_in[3];
    const float* bx   = (const float*)d_in[4];
    const float* We   = (const float*)d_in[5];
    const float* be   = (const float*)d_in[6];
    float*       out  = (float*)d_out;

    const int N = in_sizes[0] / FX;
    const int E = in_sizes[2] / FE;

    float *agg_ptr = nullptr, *wxt_ptr = nullptr, *wet_ptr = nullptr;
    cudaGetSymbolAddress((void**)&agg_ptr, g_agg);
    cudaGetSymbolAddress((void**)&wxt_ptr, g_WxT);
    cudaGetSymbolAddress((void**)&wet_ptr, g_WeT);

    // Lazy one-time creation of side stream + events.
    static cudaStream_t s_side = nullptr;
    static cudaEvent_t  s_fork = nullptr, s_join = nullptr;
    static bool s_tried = false;
    if (!s_tried) {
        s_tried = true;
        if (cudaStreamCreateWithFlags(&s_side, cudaStreamNonBlocking) != cudaSuccess)
            s_side = nullptr;
        if (s_side) {
            if (cudaEventCreateWithFlags(&s_fork, cudaEventDisableTiming) != cudaSuccess ||
                cudaEventCreateWithFlags(&s_join, cudaEventDisableTiming) != cudaSuccess)
                s_side = nullptr;
        }
    }

    // 0) fused prep: detect + transpose weights + zero agg
    int n4 = N * FE / 4;
    int prep_blocks = PREP_FIXED + (n4 + 255) / 256;
    prep_kernel<<<prep_blocks, 256>>>((const long long*)eidx, Wx, We, E, N, n4);

    int gb = (N + 127) / 128;
    int E8 = E * 8;

    if (s_side) {
        // fork: gemm128 runs concurrently with the scatter chain
        cudaEventRecord(s_fork, 0);
        cudaStreamWaitEvent(s_side, s_fork, 0);
        gemm_mma<FX, 128><<<dim3(gb, 1), 256, 0, s_side>>>(x, wxt_ptr, bx, out, N, 0);
        cudaEventRecord(s_join, s_side);

        scatter_kernel<<<(E8 + 255) / 256, 256>>>(
            reinterpret_cast<const float4*>(ea), eidx, E8, N);
        gemm_mma<FE, 64><<<dim3(gb, 2), 256>>>(agg_ptr, wet_ptr, be, out, N, 128);

        cudaStreamWaitEvent(0, s_join, 0);
    } else {
        scatter_kernel<<<(E8 + 255) / 256, 256>>>(
            reinterpret_cast<const float4*>(ea), eidx, E8, N);
        gemm_mma<FX, 128><<<dim3(gb, 1), 256>>>(x, wxt_ptr, bx, out, N, 0);
        gemm_mma<FE, 64><<<dim3(gb, 2), 256>>>(agg_ptr, wet_ptr, be, out, N, 128);
    }
}

// round 9
// speedup vs baseline: 2.1983x; 1.0104x over previous
#include <cuda_runtime.h>

// Problem constants (fixed for this dataset)
#define FX 128   // node feature dim / OX
#define FE 32    // edge feature dim
#define OW 256   // output row width (128 + 128)
#define MAXN 100000

// Static device scratch (no allocation allowed).
__device__ __align__(16) float g_agg[MAXN * FE];    // segment-sum result [N, FE]
__device__ __align__(16) float g_WxT[FX * FX];      // Wx transposed: [n=128][k=128]
__device__ __align__(16) float g_WeT[FX * FE];      // We transposed: [n=128][k=32]
__device__ int g_idx_is64;

__device__ __forceinline__ float cvt_tf32(float x) {
    unsigned r;
    asm("cvt.rna.tf32.f32 %0, %1;" : "=r"(r) : "f"(x));
    return __uint_as_float(r);
}

__device__ __forceinline__ void ldsm4(unsigned& r0, unsigned& r1,
                                      unsigned& r2, unsigned& r3,
                                      unsigned saddr) {
    asm volatile("ldmatrix.sync.aligned.m8n8.x4.shared.b16 {%0,%1,%2,%3}, [%4];"
                 : "=r"(r0), "=r"(r1), "=r"(r2), "=r"(r3) : "r"(saddr));
}

// ===========================================================================
// Fused prep: block 0 = index-dtype detect; blocks 1..16 = Wx transpose tiles;
// blocks 17..20 = We transpose tiles; blocks 21.. = zero g_agg.
// ===========================================================================
#define PREP_FIXED 21
__global__ void prep_kernel(const long long* __restrict__ idx64,
                            const float* __restrict__ Wx,
                            const float* __restrict__ We,
                            int E, int N, int n4) {
    const int b = blockIdx.x;
    const int t = threadIdx.x;

    if (b == 0) {
        __shared__ int bad;
        if (t == 0) bad = 0;
        __syncthreads();
        int n = E < 4096 ? E : 4096;
        for (int i = t; i < n; i += blockDim.x) {
            long long v = idx64[i];
            if (v < 0 || v >= (long long)N) bad = 1;
        }
        __syncthreads();
        if (t == 0) g_idx_is64 = bad ? 0 : 1;
        return;
    }
    if (b <= 20) {
        __shared__ float tile[32][33];
        const int tx = t & 31;
        const int ty = t >> 5;          // 0..7
        if (b <= 16) {                  // Wx [128k x 128n] -> WxT[n][k]
            int ti = b - 1;
            int tk = (ti >> 2) * 32, tn = (ti & 3) * 32;
            #pragma unroll
            for (int r = 0; r < 4; r++) {
                int row = ty + r * 8;
                tile[row][tx] = Wx[(tk + row) * FX + tn + tx];
            }
            __syncthreads();
            #pragma unroll
            for (int r = 0; r < 4; r++) {
                int row = ty + r * 8;
                g_WxT[(tn + row) * FX + tk + tx] = tile[tx][row];
            }
        } else {                        // We [32k x 128n] -> WeT[n][k]
            int tn = (b - 17) * 32;
            #pragma unroll
            for (int r = 0; r < 4; r++) {
                int row = ty + r * 8;
                tile[row][tx] = We[row * FX + tn + tx];
            }
            __syncthreads();
            #pragma unroll
            for (int r = 0; r < 4; r++) {
                int row = ty + r * 8;
                g_WeT[(tn + row) * FE + tx] = tile[tx][row];
            }
        }
        return;
    }
    int i = (b - PREP_FIXED) * blockDim.x + t;
    if (i < n4)
        reinterpret_cast<float4*>(g_agg)[i] = make_float4(0.f, 0.f, 0.f, 0.f);
}

// ===========================================================================
// Scatter-add: agg[row[e], :] += edge_attr[e, :]  (v4 RED, 1 instr / 16B)
// ===========================================================================
__global__ void scatter_kernel(const float4* __restrict__ ea,
                               const void* __restrict__ row_idx,
                               int E8, int N) {
    int tid = blockIdx.x * blockDim.x + threadIdx.x;
    if (tid >= E8) return;
    float4 v = ea[tid];
    int e = tid >> 3;
    int q = tid & 7;
    long long r;
    if (g_idx_is64)
        r = ((const long long*)row_idx)[e];
    else
        r = (long long)((const int*)row_idx)[e];
    if (r < 0 || r >= (long long)N) return;
    float* dst = g_agg + r * FE + q * 4;
    asm volatile("red.global.add.v4.f32 [%0], {%1, %2, %3, %4};"
                 :: "l"(dst), "f"(v.x), "f"(v.y), "f"(v.z), "f"(v.w)
                 : "memory");
}

// ===========================================================================
// Tensor-core GEMM via mma.sync.m16n8k8.tf32 + ldmatrix fragment loads.
// C[m, col0 + nb0 + n] = relu(sum_k A[m,k] * Bt[n,k] + bias[nb0+n])
// CTA tile 128(M) x BN(N); 256 thr = 8 warps as 4(M) x 2(N).
// ===========================================================================
template<int K, int BN>
__global__ __launch_bounds__(256) void gemm_mma(
    const float* __restrict__ A, const float* __restrict__ Bt,
    const float* __restrict__ bias, float* __restrict__ C,
    int M, int col0)
{
    constexpr int BK = 32;
    constexpr int NCHUNK = K / BK;
    constexpr int NFC = BN / 16;           // n-fragments per warp
    constexpr int LDS = BK + 4;            // padded row stride (floats)
    __shared__ __align__(16) float As[128][LDS];
    __shared__ __align__(16) float Bs[BN][LDS];

    const int tid  = threadIdx.x;
    const int wid  = tid >> 5;
    const int lane = tid & 31;
    const int g = lane >> 2;
    const int t = lane & 3;
    const int wm0 = (wid & 3) * 32;
    const int wn0 = (wid >> 2) * (BN / 2);
    const int m0 = blockIdx.x * 128;
    const int nb0 = blockIdx.y * BN;

    // ldmatrix per-lane base addresses (matid = lane/8, lr = lane%8):
    //   A mat layout: rows wm0 + mf*16 + (matid&1)*8 + lr, col (matid>>1)*4
    //   B mat layout (per nf-pair p): rows wn0 + p*16 + (matid>>1)*8 + lr,
    //                                 col (matid&1)*4
    const int matid = lane >> 3;
    const int lr    = lane & 7;
    const unsigned as_base = (unsigned)__cvta_generic_to_shared(&As[0][0]);
    const unsigned bs_base = (unsigned)__cvta_generic_to_shared(&Bs[0][0]);
    const unsigned aAddr = as_base +
        ((wm0 + (matid & 1) * 8 + lr) * LDS + (matid >> 1) * 4) * 4u;
    unsigned bAddr[NFC / 2];
    #pragma unroll
    for (int p = 0; p < NFC / 2; p++)
        bAddr[p] = bs_base +
            ((wn0 + p * 16 + (matid >> 1) * 8 + lr) * LDS + (matid & 1) * 4) * 4u;

    float acc[2][NFC][4];
    #pragma unroll
    for (int mf = 0; mf < 2; mf++)
        #pragma unroll
        for (int nf = 0; nf < NFC; nf++)
            #pragma unroll
            for (int c = 0; c < 4; c++)
                acc[mf][nf][c] = 0.f;

    for (int ch = 0; ch < NCHUNK; ch++) {
        const int k0 = ch * BK;
        // A chunk: 128 rows x 32 cols = 1024 float4, 4/thread.
        #pragma unroll
        for (int i = 0; i < 4; i++) {
            int idx = tid + i * 256;
            int row = idx >> 3;
            int c4  = (idx & 7) * 4;
            int m = m0 + row;
            float4 v = make_float4(0.f, 0.f, 0.f, 0.f);
            if (m < M)
                v = *reinterpret_cast<const float4*>(A + (long long)m * K + k0 + c4);
            v.x = cvt_tf32(v.x); v.y = cvt_tf32(v.y);
            v.z = cvt_tf32(v.z); v.w = cvt_tf32(v.w);
            *reinterpret_cast<float4*>(&As[row][c4]) = v;
        }
        // B chunk: BN rows x 32 cols.
        #pragma unroll
        for (int i = 0; i < BN / 32; i++) {
            int idx = tid + i * 256;
            int row = idx >> 3;
            int c4  = (idx & 7) * 4;
            float4 v = *reinterpret_cast<const float4*>(
                Bt + (long long)(nb0 + row) * K + k0 + c4);
            v.x = cvt_tf32(v.x); v.y = cvt_tf32(v.y);
            v.z = cvt_tf32(v.z); v.w = cvt_tf32(v.w);
            *reinterpret_cast<float4*>(&Bs[row][c4]) = v;
        }
        __syncthreads();

        #pragma unroll
        for (int kk = 0; kk < BK / 8; kk++) {
            const unsigned koff = kk * 32u;   // 8 floats = 32 bytes
            // B fragments via ldmatrix: one x4 per nf-pair.
            unsigned bf[NFC][2];
            #pragma unroll
            for (int p = 0; p < NFC / 2; p++)
                ldsm4(bf[p * 2][0], bf[p * 2][1], bf[p * 2 + 1][0], bf[p * 2 + 1][1],
                      bAddr[p] + koff);
            // A fragments + MMA per mf.
            #pragma unroll
            for (int mf = 0; mf < 2; mf++) {
                unsigned a0, a1, a2, a3;
                ldsm4(a0, a1, a2, a3, aAddr + mf * (16 * LDS * 4u) + koff);
                #pragma unroll
                for (int nf = 0; nf < NFC; nf++) {
                    asm volatile(
                        "mma.sync.aligned.m16n8k8.row.col.f32.tf32.tf32.f32 "
                        "{%0,%1,%2,%3}, {%4,%5,%6,%7}, {%8,%9}, {%0,%1,%2,%3};"
                        : "+f"(acc[mf][nf][0]), "+f"(acc[mf][nf][1]),
                          "+f"(acc[mf][nf][2]), "+f"(acc[mf][nf][3])
                        : "r"(a0), "r"(a1), "r"(a2), "r"(a3),
                          "r"(bf[nf][0]), "r"(bf[nf][1]));
                }
            }
        }
        __syncthreads();
    }

    #pragma unroll
    for (int mf = 0; mf < 2; mf++) {
        #pragma unroll
        for (int rr = 0; rr < 2; rr++) {
            int m = m0 + wm0 + mf * 16 + g + rr * 8;
            if (m >= M) continue;
            float* dst = C + (long long)m * OW + col0 + nb0 + wn0;
            const float* bp = bias + nb0 + wn0;
            #pragma unroll
            for (int nf = 0; nf < NFC; nf++) {
                int c = nf * 8 + 2 * t;
                float2 bb = *reinterpret_cast<const float2*>(bp + c);
                float2 o;
                o.x = fmaxf(acc[mf][nf][rr * 2 + 0] + bb.x, 0.f);
                o.y = fmaxf(acc[mf][nf][rr * 2 + 1] + bb.y, 0.f);
                *reinterpret_cast<float2*>(dst + c) = o;
            }
        }
    }
}

// ===========================================================================
extern "C" void kernel_launch(void* const* d_in, const int* in_sizes, int n_in,
                              void* d_out, int out_size) {
    const float* x    = (const float*)d_in[0];
    const void*  eidx = d_in[1];
    const float* ea   = (const float*)d_in[2];
    const float* Wx   = (const float*)d_in[3];
    const float* bx   = (const float*)d_in[4];
    const float* We   = (const float*)d_in[5];
    const float* be   = (const float*)d_in[6];
    float*       out  = (float*)d_out;

    const int N = in_sizes[0] / FX;
    const int E = in_sizes[2] / FE;

    float *agg_ptr = nullptr, *wxt_ptr = nullptr, *wet_ptr = nullptr;
    cudaGetSymbolAddress((void**)&agg_ptr, g_agg);
    cudaGetSymbolAddress((void**)&wxt_ptr, g_WxT);
    cudaGetSymbolAddress((void**)&wet_ptr, g_WeT);

    // Lazy one-time creation of side stream + events.
    static cudaStream_t s_side = nullptr;
    static cudaEvent_t  s_fork = nullptr, s_join = nullptr;
    static bool s_tried = false;
    if (!s_tried) {
        s_tried = true;
        if (cudaStreamCreateWithFlags(&s_side, cudaStreamNonBlocking) != cudaSuccess)
            s_side = nullptr;
        if (s_side) {
            if (cudaEventCreateWithFlags(&s_fork, cudaEventDisableTiming) != cudaSuccess ||
                cudaEventCreateWithFlags(&s_join, cudaEventDisableTiming) != cudaSuccess)
                s_side = nullptr;
        }
    }

    // 0) fused prep: detect + transpose weights + zero agg
    int n4 = N * FE / 4;
    int prep_blocks = PREP_FIXED + (n4 + 255) / 256;
    prep_kernel<<<prep_blocks, 256>>>((const long long*)eidx, Wx, We, E, N, n4);

    int gb = (N + 127) / 128;
    int E8 = E * 8;

    if (s_side) {
        // fork: gemm128 runs concurrently with the scatter chain
        cudaEventRecord(s_fork, 0);
        cudaStreamWaitEvent(s_side, s_fork, 0);
        gemm_mma<FX, 128><<<dim3(gb, 1), 256, 0, s_side>>>(x, wxt_ptr, bx, out, N, 0);
        cudaEventRecord(s_join, s_side);

        scatter_kernel<<<(E8 + 255) / 256, 256>>>(
            reinterpret_cast<const float4*>(ea), eidx, E8, N);
        gemm_mma<FE, 64><<<dim3(gb, 2), 256>>>(agg_ptr, wet_ptr, be, out, N, 128);

        cudaStreamWaitEvent(0, s_join, 0);
    } else {
        scatter_kernel<<<(E8 + 255) / 256, 256>>>(
            reinterpret_cast<const float4*>(ea), eidx, E8, N);
        gemm_mma<FX, 128><<<dim3(gb, 1), 256>>>(x, wxt_ptr, bx, out, N, 0);
        gemm_mma<FE, 64><<<dim3(gb, 2), 256>>>(agg_ptr, wet_ptr, be, out, N, 128);
    }
}

// round 10
// speedup vs baseline: 2.5101x; 1.1418x over previous
#include <cuda_runtime.h>

// Problem constants (fixed for this dataset)
#define FX 128   // node feature dim / OX
#define FE 32    // edge feature dim
#define OW 256   // output row width (128 + 128)
#define MAXN 100000

// Static device scratch (no allocation allowed).
__device__ __align__(16) float g_agg[MAXN * FE];    // segment-sum result [N, FE]
__device__ __align__(16) float g_WxT[FX * FX];      // Wx transposed: [n=128][k=128]
__device__ __align__(16) float g_WeT[FX * FE];      // We transposed: [n=128][k=32]
__device__ int g_idx_is64;

__device__ __forceinline__ float cvt_tf32(float x) {
    unsigned r;
    asm("cvt.rna.tf32.f32 %0, %1;" : "=r"(r) : "f"(x));
    return __uint_as_float(r);
}

__device__ __forceinline__ void ldsm4(unsigned& r0, unsigned& r1,
                                      unsigned& r2, unsigned& r3,
                                      unsigned saddr) {
    asm volatile("ldmatrix.sync.aligned.m8n8.x4.shared.b16 {%0,%1,%2,%3}, [%4];"
                 : "=r"(r0), "=r"(r1), "=r"(r2), "=r"(r3) : "r"(saddr));
}

// ===========================================================================
// Fused prep: block 0 = index-dtype detect; blocks 1..16 = Wx transpose tiles;
// blocks 17..20 = We transpose tiles; blocks 21.. = zero g_agg.
// ===========================================================================
#define PREP_FIXED 21
__global__ void prep_kernel(const long long* __restrict__ idx64,
                            const float* __restrict__ Wx,
                            const float* __restrict__ We,
                            int E, int N, int n4) {
    const int b = blockIdx.x;
    const int t = threadIdx.x;

    if (b == 0) {
        __shared__ int bad;
        if (t == 0) bad = 0;
        __syncthreads();
        int n = E < 4096 ? E : 4096;
        for (int i = t; i < n; i += blockDim.x) {
            long long v = idx64[i];
            if (v < 0 || v >= (long long)N) bad = 1;
        }
        __syncthreads();
        if (t == 0) g_idx_is64 = bad ? 0 : 1;
        return;
    }
    if (b <= 20) {
        __shared__ float tile[32][33];
        const int tx = t & 31;
        const int ty = t >> 5;          // 0..7
        if (b <= 16) {                  // Wx [128k x 128n] -> WxT[n][k]
            int ti = b - 1;
            int tk = (ti >> 2) * 32, tn = (ti & 3) * 32;
            #pragma unroll
            for (int r = 0; r < 4; r++) {
                int row = ty + r * 8;
                tile[row][tx] = Wx[(tk + row) * FX + tn + tx];
            }
            __syncthreads();
            #pragma unroll
            for (int r = 0; r < 4; r++) {
                int row = ty + r * 8;
                g_WxT[(tn + row) * FX + tk + tx] = tile[tx][row];
            }
        } else {                        // We [32k x 128n] -> WeT[n][k]
            int tn = (b - 17) * 32;
            #pragma unroll
            for (int r = 0; r < 4; r++) {
                int row = ty + r * 8;
                tile[row][tx] = We[row * FX + tn + tx];
            }
            __syncthreads();
            #pragma unroll
            for (int r = 0; r < 4; r++) {
                int row = ty + r * 8;
                g_WeT[(tn + row) * FE + tx] = tile[tx][row];
            }
        }
        return;
    }
    int i = (b - PREP_FIXED) * blockDim.x + t;
    if (i < n4)
        reinterpret_cast<float4*>(g_agg)[i] = make_float4(0.f, 0.f, 0.f, 0.f);
}

// ===========================================================================
// Scatter-add with MLP batching: each thread processes UNITS (edge, q) chunks
// spaced one grid apart; all loads front-batched for memory-level parallelism.
// ===========================================================================
#define SC_UNITS 4
__global__ void scatter_kernel(const float4* __restrict__ ea,
                               const void* __restrict__ row_idx,
                               int E8, int stride, int N) {
    const int tid = blockIdx.x * blockDim.x + threadIdx.x;
    const bool is64 = (g_idx_is64 != 0);

    float4 v[SC_UNITS];
    long long r[SC_UNITS];
    // Front-batched independent loads (index + data) -> MLP ~ 2*SC_UNITS.
    #pragma unroll
    for (int i = 0; i < SC_UNITS; i++) {
        int u = tid + i * stride;
        if (u < E8) {
            int e = u >> 3;
            v[i] = ea[u];
            r[i] = is64 ? ((const long long*)row_idx)[e]
                        : (long long)((const int*)row_idx)[e];
        } else {
            r[i] = -1;
        }
    }
    #pragma unroll
    for (int i = 0; i < SC_UNITS; i++) {
        if (r[i] < 0 || r[i] >= (long long)N) continue;
        int u = tid + i * stride;
        float* dst = g_agg + r[i] * FE + (u & 7) * 4;
        asm volatile("red.global.add.v4.f32 [%0], {%1, %2, %3, %4};"
                     :: "l"(dst), "f"(v[i].x), "f"(v[i].y), "f"(v[i].z), "f"(v[i].w)
                     : "memory");
    }
}

// ===========================================================================
// Tensor-core GEMM via mma.sync.m16n8k8.tf32 + ldmatrix fragment loads.
// C[m, col0 + nb0 + n] = relu(sum_k A[m,k] * Bt[n,k] + bias[nb0+n])
// CTA tile BM(M) x BN(N); 256 thr = 8 warps as 4(M) x 2(N).
// ===========================================================================
template<int K, int BM, int BN>
__global__ __launch_bounds__(256) void gemm_mma(
    const float* __restrict__ A, const float* __restrict__ Bt,
    const float* __restrict__ bias, float* __restrict__ C,
    int M, int col0)
{
    constexpr int BK = 32;
    constexpr int NCHUNK = K / BK;
    constexpr int MFC = BM / 64;           // m16-fragments per warp (BM/4/16)
    constexpr int NFC = BN / 16;           // n8-fragments per warp (BN/2/8)
    constexpr int LDS = BK + 4;            // padded row stride (floats)
    __shared__ __align__(16) float As[BM][LDS];
    __shared__ __align__(16) float Bs[BN][LDS];

    const int tid  = threadIdx.x;
    const int wid  = tid >> 5;
    const int lane = tid & 31;
    const int g = lane >> 2;
    const int t = lane & 3;
    const int wm0 = (wid & 3) * (BM / 4);
    const int wn0 = (wid >> 2) * (BN / 2);
    const int m0 = blockIdx.x * BM;
    const int nb0 = blockIdx.y * BN;

    // ldmatrix per-lane base addresses (matid = lane/8, lr = lane%8).
    const int matid = lane >> 3;
    const int lr    = lane & 7;
    const unsigned as_base = (unsigned)__cvta_generic_to_shared(&As[0][0]);
    const unsigned bs_base = (unsigned)__cvta_generic_to_shared(&Bs[0][0]);
    const unsigned aAddr = as_base +
        ((wm0 + (matid & 1) * 8 + lr) * LDS + (matid >> 1) * 4) * 4u;
    unsigned bAddr[NFC / 2];
    #pragma unroll
    for (int p = 0; p < NFC / 2; p++)
        bAddr[p] = bs_base +
            ((wn0 + p * 16 + (matid >> 1) * 8 + lr) * LDS + (matid & 1) * 4) * 4u;

    float acc[MFC][NFC][4];
    #pragma unroll
    for (int mf = 0; mf < MFC; mf++)
        #pragma unroll
        for (int nf = 0; nf < NFC; nf++)
            #pragma unroll
            for (int c = 0; c < 4; c++)
                acc[mf][nf][c] = 0.f;

    for (int ch = 0; ch < NCHUNK; ch++) {
        const int k0 = ch * BK;
        // A chunk: BM rows x 32 cols, float4 loads.
        #pragma unroll
        for (int i = 0; i < BM / 32; i++) {
            int idx = tid + i * 256;
            int row = idx >> 3;
            int c4  = (idx & 7) * 4;
            int m = m0 + row;
            float4 v = make_float4(0.f, 0.f, 0.f, 0.f);
            if (m < M)
                v = *reinterpret_cast<const float4*>(A + (long long)m * K + k0 + c4);
            v.x = cvt_tf32(v.x); v.y = cvt_tf32(v.y);
            v.z = cvt_tf32(v.z); v.w = cvt_tf32(v.w);
            *reinterpret_cast<float4*>(&As[row][c4]) = v;
        }
        // B chunk: BN rows x 32 cols.
        #pragma unroll
        for (int i = 0; i < BN / 32; i++) {
            int idx = tid + i * 256;
            int row = idx >> 3;
            int c4  = (idx & 7) * 4;
            float4 v = *reinterpret_cast<const float4*>(
                Bt + (long long)(nb0 + row) * K + k0 + c4);
            v.x = cvt_tf32(v.x); v.y = cvt_tf32(v.y);
            v.z = cvt_tf32(v.z); v.w = cvt_tf32(v.w);
            *reinterpret_cast<float4*>(&Bs[row][c4]) = v;
        }
        __syncthreads();

        #pragma unroll
        for (int kk = 0; kk < BK / 8; kk++) {
            const unsigned koff = kk * 32u;   // 8 floats = 32 bytes
            unsigned bf[NFC][2];
            #pragma unroll
            for (int p = 0; p < NFC / 2; p++)
                ldsm4(bf[p * 2][0], bf[p * 2][1], bf[p * 2 + 1][0], bf[p * 2 + 1][1],
                      bAddr[p] + koff);
            #pragma unroll
            for (int mf = 0; mf < MFC; mf++) {
                unsigned a0, a1, a2, a3;
                ldsm4(a0, a1, a2, a3, aAddr + mf * (16 * LDS * 4u) + koff);
                #pragma unroll
                for (int nf = 0; nf < NFC; nf++) {
                    asm volatile(
                        "mma.sync.aligned.m16n8k8.row.col.f32.tf32.tf32.f32 "
                        "{%0,%1,%2,%3}, {%4,%5,%6,%7}, {%8,%9}, {%0,%1,%2,%3};"
                        : "+f"(acc[mf][nf][0]), "+f"(acc[mf][nf][1]),
                          "+f"(acc[mf][nf][2]), "+f"(acc[mf][nf][3])
                        : "r"(a0), "r"(a1), "r"(a2), "r"(a3),
                          "r"(bf[nf][0]), "r"(bf[nf][1]));
                }
            }
        }
        __syncthreads();
    }

    #pragma unroll
    for (int mf = 0; mf < MFC; mf++) {
        #pragma unroll
        for (int rr = 0; rr < 2; rr++) {
            int m = m0 + wm0 + mf * 16 + g + rr * 8;
            if (m >= M) continue;
            float* dst = C + (long long)m * OW + col0 + nb0 + wn0;
            const float* bp = bias + nb0 + wn0;
            #pragma unroll
            for (int nf = 0; nf < NFC; nf++) {
                int c = nf * 8 + 2 * t;
                float2 bb = *reinterpret_cast<const float2*>(bp + c);
                float2 o;
                o.x = fmaxf(acc[mf][nf][rr * 2 + 0] + bb.x, 0.f);
                o.y = fmaxf(acc[mf][nf][rr * 2 + 1] + bb.y, 0.f);
                *reinterpret_cast<float2*>(dst + c) = o;
            }
        }
    }
}

// ===========================================================================
extern "C" void kernel_launch(void* const* d_in, const int* in_sizes, int n_in,
                              void* d_out, int out_size) {
    const float* x    = (const float*)d_in[0];
    const void*  eidx = d_in[1];
    const float* ea   = (const float*)d_in[2];
    const float* Wx   = (const float*)d_in[3];
    const float* bx   = (const float*)d_in[4];
    const float* We   = (const float*)d_in[5];
    const float* be   = (const float*)d_in[6];
    float*       out  = (float*)d_out;

    const int N = in_sizes[0] / FX;
    const int E = in_sizes[2] / FE;

    float *agg_ptr = nullptr, *wxt_ptr = nullptr, *wet_ptr = nullptr;
    cudaGetSymbolAddress((void**)&agg_ptr, g_agg);
    cudaGetSymbolAddress((void**)&wxt_ptr, g_WxT);
    cudaGetSymbolAddress((void**)&wet_ptr, g_WeT);

    // Lazy one-time creation of side stream + events.
    static cudaStream_t s_side = nullptr;
    static cudaEvent_t  s_fork = nullptr, s_join = nullptr;
    static bool s_tried = false;
    if (!s_tried) {
        s_tried = true;
        if (cudaStreamCreateWithFlags(&s_side, cudaStreamNonBlocking) != cudaSuccess)
            s_side = nullptr;
        if (s_side) {
            if (cudaEventCreateWithFlags(&s_fork, cudaEventDisableTiming) != cudaSuccess ||
                cudaEventCreateWithFlags(&s_join, cudaEventDisableTiming) != cudaSuccess)
                s_side = nullptr;
        }
    }

    // 0) fused prep: detect + transpose weights + zero agg
    int n4 = N * FE / 4;
    int prep_blocks = PREP_FIXED + (n4 + 255) / 256;
    prep_kernel<<<prep_blocks, 256>>>((const long long*)eidx, Wx, We, E, N, n4);

    int gb128 = (N + 127) / 128;
    int gb64  = (N + 63) / 64;
    int E8 = E * 8;
    int sc_threads = (E8 + SC_UNITS - 1) / SC_UNITS;
    int sc_blocks  = (sc_threads + 255) / 256;
    int sc_stride  = sc_blocks * 256;

    if (s_side) {
        // fork: gemm128 runs concurrently with the scatter chain
        cudaEventRecord(s_fork, 0);
        cudaStreamWaitEvent(s_side, s_fork, 0);
        gemm_mma<FX, 128, 128><<<dim3(gb128, 1), 256, 0, s_side>>>(x, wxt_ptr, bx, out, N, 0);
        cudaEventRecord(s_join, s_side);

        scatter_kernel<<<sc_blocks, 256>>>(
            reinterpret_cast<const float4*>(ea), eidx, E8, sc_stride, N);
        gemm_mma<FE, 64, 64><<<dim3(gb64, 2), 256>>>(agg_ptr, wet_ptr, be, out, N, 128);

        cudaStreamWaitEvent(0, s_join, 0);
    } else {
        scatter_kernel<<<sc_blocks, 256>>>(
            reinterpret_cast<const float4*>(ea), eidx, E8, sc_stride, N);
        gemm_mma<FX, 128, 128><<<dim3(gb128, 1), 256>>>(x, wxt_ptr, bx, out, N, 0);
        gemm_mma<FE, 64, 64><<<dim3(gb64, 2), 256>>>(agg_ptr, wet_ptr, be, out, N, 128);
    }
}